// round 16
// baseline (speedup 1.0000x reference)
#include <cuda_runtime.h>
#include <cuda_bf16.h>
#include <math.h>

// Problem dims
#define H   1024
#define H3  3072
#define V   50257
#define L   50
#define ENC 2048

// Scratch layout (floats)
#define A_OFF      0
#define GH_OFF     1024
#define B_OFF      4096
#define XIN_OFF    55296
#define XPRE_OFF   58368
#define GI_OFF     59392
#define HNEW_OFF   62464
#define SE_OFF     63600
#define SUM_OFF    63520
#define SCRATCH_ELEMS 65536

__device__ float g_scratch[SCRATCH_ELEMS];

// Self-resetting grid barriers; zero at load, last departer resets -> replay-safe.
__device__ unsigned g_arrive[8];
__device__ unsigned g_depart[8];
// P1 work-stealing counter; reset after barrier 1 each execution -> replay-safe.
__device__ unsigned g_unit_ctr;

__device__ __forceinline__ void grid_bar(int i, unsigned n) {
    __threadfence();
    __syncthreads();
    if (threadIdx.x == 0) {
        atomicAdd(&g_arrive[i], 1u);
        while (*(volatile unsigned*)&g_arrive[i] < n) __nanosleep(64);
        unsigned d = atomicAdd(&g_depart[i], 1u);
        if (d == n - 1u) {
            *(volatile unsigned*)&g_depart[i] = 0u;
            __threadfence();
            *(volatile unsigned*)&g_arrive[i] = 0u;
        }
    }
    __syncthreads();
    __threadfence();
}

// ---------------------------------------------------------------------------
// ONE persistent kernel: 296 blocks x 256 threads (2/SM co-resident).
// P0 init -> P1 {h-GEMVs + enc GEMM, work-stealing} -> P2 scores ->
// P3 softmax/apply -> P4 comb -> P5 gih -> P6 GRU -> P7 vocab GEMV +
// fused log-softmax (full-K per thread, single final write).
// ---------------------------------------------------------------------------
#define LB 10
#define P1_UNITS 768
__global__ void __launch_bounds__(256, 2)
fused_all_kernel(const float* __restrict__ hidden,
                 const float* __restrict__ enc,
                 const float* __restrict__ emb,
                 const int*   __restrict__ idx,
                 const float* __restrict__ attn_w_W,
                 const float* __restrict__ attn_w_b,
                 const float* __restrict__ attn_v_W,
                 const float* __restrict__ attn_v_b,
                 const float* __restrict__ comb_W,
                 const float* __restrict__ comb_b,
                 const float* __restrict__ gru_wih,
                 const float* __restrict__ gru_bih,
                 const float* __restrict__ gru_whh,
                 const float* __restrict__ gru_bhh,
                 const float* __restrict__ out_W,
                 const float* __restrict__ out_b,
                 float* __restrict__ s,
                 float* __restrict__ logp_out,
                 float* __restrict__ hnew_out,
                 float* __restrict__ attw_out) {
    __shared__ float sm[704];      // enc tile (640) / softmax se+sw (100)
    __shared__ float ws[8];
    __shared__ float hs[H];        // h_new staging for P7
    __shared__ float lse_s;
    __shared__ unsigned s_uid;
    const unsigned NBLK = gridDim.x;     // 296
    const int bid = blockIdx.x;
    const int t = threadIdx.x;
    const int lane = t & 31, warp = t >> 5;

    // ---- P0: biases into accumulators, zero B, gsum=0 ----
    {
        int gid = bid * 256 + t, stride = NBLK * 256;
        for (int i = gid; i < L * H; i += stride) s[B_OFF + i] = 0.f;
        for (int i = gid; i < H;    i += stride) s[A_OFF + i] = attn_w_b[i];
        for (int i = gid; i < H3;   i += stride) s[GH_OFF + i] = gru_bhh[i];
        for (int i = gid; i < H3;   i += stride) s[GI_OFF + i] = gru_bih[i];
        for (int i = gid; i < H;    i += stride) s[XPRE_OFF + i] = comb_b[i];
        for (int i = gid; i < L;    i += stride) s[SE_OFF + i] = attn_v_b[0];
        if (gid == 0) s[SUM_OFF] = 0.f;
    }
    grid_bar(0, NBLK);

    // ---- P1 (work-stealing): units 0..127 dual h-GEMV; 128..767 enc GEMM --
    for (;;) {
        __syncthreads();
        if (t == 0) s_uid = atomicAdd(&g_unit_ctr, 1u);
        __syncthreads();
        unsigned u = s_uid;
        if (u >= P1_UNITS) break;
        if (u < 128) {
            int ju = u & 3, ku = u >> 2;           // 32 k-splits of 32
            const float* W; float* out; int N, jb;
            if (ju == 0) { W = attn_w_W; out = s + A_OFF;  N = 1024; jb = 0; }
            else         { W = gru_whh;  out = s + GH_OFF; N = 3072; jb = (ju - 1) * 1024; }
            int j = jb + t * 4;
            int k0 = ku * 32;
            const float* Wp = W + (size_t)k0 * N + j;
            float a0 = 0.f, a1 = 0.f, a2 = 0.f, a3 = 0.f;
#pragma unroll 8
            for (int k = 0; k < 32; ++k) {
                float xv = __ldg(&hidden[k0 + k]);
                float4 w = *(const float4*)Wp;
                a0 = fmaf(xv, w.x, a0); a1 = fmaf(xv, w.y, a1);
                a2 = fmaf(xv, w.z, a2); a3 = fmaf(xv, w.w, a3);
                Wp += N;
            }
            atomicAdd(&out[j],     a0); atomicAdd(&out[j + 1], a1);
            atomicAdd(&out[j + 2], a2); atomicAdd(&out[j + 3], a3);
        } else {
            int e = u - 128;                        // 640 units: 4j x 32k x 5l
            int uj = e & 3, uk = (e >> 2) & 31, ul = e >> 7;
            int j = uj * 256 + t, k0 = uk * 64, l0 = ul * LB;
            for (int i = t; i < LB * 64; i += 256) {
                int l = i >> 6, kk = i & 63;
                sm[i] = enc[(l0 + l) * ENC + k0 + kk];
            }
            __syncthreads();
            float acc[LB];
#pragma unroll
            for (int l = 0; l < LB; ++l) acc[l] = 0.f;
            const float* Wp = attn_w_W + (size_t)H * H + (size_t)k0 * H + j;
#pragma unroll 8
            for (int kk = 0; kk < 64; ++kk) {
                float w = Wp[(size_t)kk * H];
#pragma unroll
                for (int l = 0; l < LB; ++l)
                    acc[l] = fmaf(w, sm[l * 64 + kk], acc[l]);
            }
#pragma unroll
            for (int l = 0; l < LB; ++l)
                atomicAdd(&s[B_OFF + (l0 + l) * H + j], acc[l]);
        }
    }
    grid_bar(1, NBLK);
    if (bid == 0 && t == 0) g_unit_ctr = 0u;        // replay-safe reset

    // ---- P2: scores se[l] += relu(a + B[l]) @ v  (100 half-units) ----
    if (bid < 100) {
        int l = bid >> 1, half = bid & 1;
        const float* a  = s + A_OFF + half * 512;
        const float* Bl = s + B_OFF + l * H + half * 512;
        const float* vv = attn_v_W + half * 512;
        float p = 0.f;
#pragma unroll
        for (int jj = t; jj < 512; jj += 256)
            p = fmaf(fmaxf(a[jj] + Bl[jj], 0.f), vv[jj], p);
#pragma unroll
        for (int o = 16; o; o >>= 1) p += __shfl_xor_sync(0xffffffffu, p, o);
        if (lane == 0) ws[warp] = p;
        __syncthreads();
        if (t == 0) {
            float acc = ws[0];
#pragma unroll
            for (int w = 1; w < 8; ++w) acc += ws[w];
            atomicAdd(&s[SE_OFF + l], acc);
        }
    }
    grid_bar(2, NBLK);

    // ---- P3: softmax + attn_applied (blocks 0..7), attw/emb (block 8) ----
    if (bid <= 8) {
        float* se = sm;        // [50]
        float* sw = sm + 64;   // [50]
        __syncthreads();
        if (t < L) se[t] = s[SE_OFF + t];
        __syncthreads();
        if (t < L) {
            float m = -3.0e38f;
#pragma unroll
            for (int l = 0; l < L; ++l) m = fmaxf(m, se[l]);
            float sum = 0.f;
#pragma unroll
            for (int l = 0; l < L; ++l) sum += expf(se[l] - m);
            sw[t] = expf(se[t] - m) / sum;
        }
        __syncthreads();
        float* xin = s + XIN_OFF;
        if (bid < 8) {
            int col = bid * 256 + t;               // 0..2047
            float acc = 0.f;
#pragma unroll 10
            for (int l = 0; l < L; ++l)
                acc = fmaf(sw[l], enc[l * ENC + col], acc);
            xin[H + col] = acc;
        } else {
            if (t < L) attw_out[t] = sw[t];
            int id = idx[0];
            for (int i = t; i < H; i += 256)
                xin[i] = emb[(size_t)id * H + i];
        }
    }
    grid_bar(3, NBLK);

    // ---- P4: xpre += xin @ comb_W   (64 k-splits of 48) ----
    if (bid < 64) {
        int j = t * 4;
        int k0 = bid * 48;
        const float* Wp = comb_W + (size_t)k0 * H + j;
        float a0 = 0.f, a1 = 0.f, a2 = 0.f, a3 = 0.f;
#pragma unroll 8
        for (int k = 0; k < 48; ++k) {
            float xv = s[XIN_OFF + k0 + k];
            float4 w = *(const float4*)Wp;
            a0 = fmaf(xv, w.x, a0); a1 = fmaf(xv, w.y, a1);
            a2 = fmaf(xv, w.z, a2); a3 = fmaf(xv, w.w, a3);
            Wp += H;
        }
        atomicAdd(&s[XPRE_OFF + j],     a0); atomicAdd(&s[XPRE_OFF + j + 1], a1);
        atomicAdd(&s[XPRE_OFF + j + 2], a2); atomicAdd(&s[XPRE_OFF + j + 3], a3);
    }
    grid_bar(4, NBLK);

    // ---- P5: gi += relu(xpre) @ gru_wih  (3 j-tiles x 32 k-splits) ----
    if (bid < 96) {
        int ju = bid % 3, ku = bid / 3;
        int j = ju * 1024 + t * 4;
        int k0 = ku * 32;
        const float* Wp = gru_wih + (size_t)k0 * H3 + j;
        float a0 = 0.f, a1 = 0.f, a2 = 0.f, a3 = 0.f;
#pragma unroll 8
        for (int k = 0; k < 32; ++k) {
            float xv = fmaxf(s[XPRE_OFF + k0 + k], 0.f);
            float4 w = *(const float4*)Wp;
            a0 = fmaf(xv, w.x, a0); a1 = fmaf(xv, w.y, a1);
            a2 = fmaf(xv, w.z, a2); a3 = fmaf(xv, w.w, a3);
            Wp += H3;
        }
        atomicAdd(&s[GI_OFF + j],     a0); atomicAdd(&s[GI_OFF + j + 1], a1);
        atomicAdd(&s[GI_OFF + j + 2], a2); atomicAdd(&s[GI_OFF + j + 3], a3);
    }
    grid_bar(5, NBLK);

    // ---- P6: GRU gates -> h_new (blocks 0..3) ----
    if (bid < 4) {
        int i = bid * 256 + t;
        const float* gi = s + GI_OFF;
        const float* gh = s + GH_OFF;
        float r = 1.f / (1.f + expf(-(gi[i] + gh[i])));
        float z = 1.f / (1.f + expf(-(gi[H + i] + gh[H + i])));
        float n = tanhf(gi[2 * H + i] + r * gh[2 * H + i]);
        float hn = (1.f - z) * n + z * hidden[i];
        s[HNEW_OFF + i] = hn;
        hnew_out[i] = hn;
    }
    grid_bar(6, NBLK);

    // ---- P7: vocab GEMV (full-K per thread, 1 col) + fused log-softmax ----
    for (int i = t; i < H; i += 256) hs[i] = s[HNEW_OFF + i];
    __syncthreads();

    int j = bid * 256 + t;             // blocks 0..196 cover V
    bool valid = (j < V);
    float acc = 0.f;
    if (valid) {
        acc = out_b[j];
        const float* Wp = out_W + j;
#pragma unroll 8
        for (int k = 0; k < H; ++k) {
            acc = fmaf(hs[k], *Wp, acc);
            Wp += V;
        }
    }
    float ex = valid ? expf(acc) : 0.f;
#pragma unroll
    for (int o = 16; o; o >>= 1) ex += __shfl_xor_sync(0xffffffffu, ex, o);
    if ((t & 31) == 0 && ex != 0.f) atomicAdd(&s[SUM_OFF], ex);

    // barrier 7 with lse pickup between spin and depart
    __threadfence();
    __syncthreads();
    if (t == 0) {
        atomicAdd(&g_arrive[7], 1u);
        while (*(volatile unsigned*)&g_arrive[7] < NBLK) __nanosleep(64);
        lse_s = logf(*(volatile float*)&s[SUM_OFF]);
        unsigned d = atomicAdd(&g_depart[7], 1u);
        if (d == NBLK - 1u) {
            *(volatile unsigned*)&g_depart[7] = 0u;
            __threadfence();
            *(volatile unsigned*)&g_arrive[7] = 0u;
        }
    }
    __syncthreads();

    if (valid) logp_out[j] = acc - lse_s;
}

// ---------------------------------------------------------------------------
extern "C" void kernel_launch(void* const* d_in, const int* in_sizes, int n_in,
                              void* d_out, int out_size) {
    const int*   idx      = (const int*)d_in[0];
    const float* hidden   = (const float*)d_in[1];
    const float* enc      = (const float*)d_in[2];
    const float* emb      = (const float*)d_in[3];
    const float* attn_w_W = (const float*)d_in[4];
    const float* attn_w_b = (const float*)d_in[5];
    const float* attn_v_W = (const float*)d_in[6];
    const float* attn_v_b = (const float*)d_in[7];
    const float* comb_W   = (const float*)d_in[8];
    const float* comb_b   = (const float*)d_in[9];
    const float* gru_wih  = (const float*)d_in[10];
    const float* gru_bih  = (const float*)d_in[11];
    const float* gru_whh  = (const float*)d_in[12];
    const float* gru_bhh  = (const float*)d_in[13];
    const float* out_W    = (const float*)d_in[14];
    const float* out_b    = (const float*)d_in[15];
    float* out = (float*)d_out;   // [V logprobs][H h_new][L attn_weights]

    float* s = nullptr;
    cudaGetSymbolAddress((void**)&s, g_scratch);

    fused_all_kernel<<<296, 256>>>(hidden, enc, emb, idx,
                                   attn_w_W, attn_w_b, attn_v_W, attn_v_b,
                                   comb_W, comb_b, gru_wih, gru_bih,
                                   gru_whh, gru_bhh, out_W, out_b,
                                   s, out, out + V, out + V + H);
}

// round 17
// speedup vs baseline: 1.4656x; 1.4656x over previous
#include <cuda_runtime.h>
#include <cuda_bf16.h>
#include <math.h>

// Problem dims
#define H   1024
#define H3  3072
#define V   50257
#define L   50
#define ENC 2048

// Scratch layout (floats)
#define A_OFF      0
#define GH_OFF     1024
#define B_OFF      4096
#define XIN_OFF    55296
#define XPRE_OFF   58368
#define GI_OFF     59392
#define HNEW_OFF   62464
#define SE_OFF     63600
#define SUM_OFF    63520
#define SCRATCH_ELEMS 65536

__device__ float g_scratch[SCRATCH_ELEMS];

// Self-resetting grid barriers; zero at load, last departer resets -> replay-safe.
__device__ unsigned g_arrive[8];
__device__ unsigned g_depart[8];

__device__ __forceinline__ void grid_bar(int i, unsigned n) {
    __threadfence();
    __syncthreads();
    if (threadIdx.x == 0) {
        atomicAdd(&g_arrive[i], 1u);
        while (*(volatile unsigned*)&g_arrive[i] < n) __nanosleep(64);
        unsigned d = atomicAdd(&g_depart[i], 1u);
        if (d == n - 1u) {
            *(volatile unsigned*)&g_depart[i] = 0u;
            __threadfence();
            *(volatile unsigned*)&g_arrive[i] = 0u;
        }
    }
    __syncthreads();
    __threadfence();
}

// ---------------------------------------------------------------------------
// Fused small-op chain (R9 configuration — best measured, ~52 us).
// 296 blocks x 256 threads (2/SM co-resident).
// ---------------------------------------------------------------------------
#define LB 10
__global__ void __launch_bounds__(256, 2)
fused_chain_kernel(const float* __restrict__ hidden,
                   const float* __restrict__ enc,
                   const float* __restrict__ emb,
                   const int*   __restrict__ idx,
                   const float* __restrict__ attn_w_W,
                   const float* __restrict__ attn_w_b,
                   const float* __restrict__ attn_v_W,
                   const float* __restrict__ attn_v_b,
                   const float* __restrict__ comb_W,
                   const float* __restrict__ comb_b,
                   const float* __restrict__ gru_wih,
                   const float* __restrict__ gru_bih,
                   const float* __restrict__ gru_whh,
                   const float* __restrict__ gru_bhh,
                   const float* __restrict__ out_b,
                   float* __restrict__ s,
                   float* __restrict__ logits,
                   float* __restrict__ hnew_out,
                   float* __restrict__ attw_out) {
    __shared__ float sm[704];
    __shared__ float ws[8];
    const unsigned NBLK = gridDim.x;     // 296
    const int bid = blockIdx.x;
    const int t = threadIdx.x;
    const int lane = t & 31, warp = t >> 5;

    // ---- P0: biases, zero B, logits=bias, gsum=0 ----
    {
        int gid = bid * 256 + t, stride = NBLK * 256;
        for (int i = gid; i < L * H; i += stride) s[B_OFF + i] = 0.f;
        for (int i = gid; i < H;    i += stride) s[A_OFF + i] = attn_w_b[i];
        for (int i = gid; i < H3;   i += stride) s[GH_OFF + i] = gru_bhh[i];
        for (int i = gid; i < H3;   i += stride) s[GI_OFF + i] = gru_bih[i];
        for (int i = gid; i < H;    i += stride) s[XPRE_OFF + i] = comb_b[i];
        for (int i = gid; i < V;    i += stride) logits[i] = out_b[i];
        for (int i = gid; i < L;    i += stride) s[SE_OFF + i] = attn_v_b[0];
        if (gid == 0) s[SUM_OFF] = 0.f;
    }
    grid_bar(0, NBLK);

    // ---- P1: units 0..127 dual h-GEMV; units 128..767 enc GEMM ----
    for (int u = bid; u < 768; u += NBLK) {
        if (u < 128) {
            int ju = u & 3, ku = u >> 2;           // 32 k-splits of 32
            const float* W; float* out; int N, jb;
            if (ju == 0) { W = attn_w_W; out = s + A_OFF;  N = 1024; jb = 0; }
            else         { W = gru_whh;  out = s + GH_OFF; N = 3072; jb = (ju - 1) * 1024; }
            int j = jb + t * 4;
            int k0 = ku * 32;
            const float* Wp = W + (size_t)k0 * N + j;
            float a0 = 0.f, a1 = 0.f, a2 = 0.f, a3 = 0.f;
#pragma unroll 8
            for (int k = 0; k < 32; ++k) {
                float xv = __ldg(&hidden[k0 + k]);
                float4 w = *(const float4*)Wp;
                a0 = fmaf(xv, w.x, a0); a1 = fmaf(xv, w.y, a1);
                a2 = fmaf(xv, w.z, a2); a3 = fmaf(xv, w.w, a3);
                Wp += N;
            }
            atomicAdd(&out[j],     a0); atomicAdd(&out[j + 1], a1);
            atomicAdd(&out[j + 2], a2); atomicAdd(&out[j + 3], a3);
        } else {
            int e = u - 128;                        // 640 units: 4j x 32k x 5l
            int uj = e & 3, uk = (e >> 2) & 31, ul = e >> 7;
            int j = uj * 256 + t, k0 = uk * 64, l0 = ul * LB;
            __syncthreads();
            for (int i = t; i < LB * 64; i += 256) {
                int l = i >> 6, kk = i & 63;
                sm[i] = enc[(l0 + l) * ENC + k0 + kk];
            }
            __syncthreads();
            float acc[LB];
#pragma unroll
            for (int l = 0; l < LB; ++l) acc[l] = 0.f;
            const float* Wp = attn_w_W + (size_t)H * H + (size_t)k0 * H + j;
#pragma unroll 8
            for (int kk = 0; kk < 64; ++kk) {
                float w = Wp[(size_t)kk * H];
#pragma unroll
                for (int l = 0; l < LB; ++l)
                    acc[l] = fmaf(w, sm[l * 64 + kk], acc[l]);
            }
#pragma unroll
            for (int l = 0; l < LB; ++l)
                atomicAdd(&s[B_OFF + (l0 + l) * H + j], acc[l]);
        }
    }
    grid_bar(1, NBLK);

    // ---- P2: scores se[l] += relu(a + B[l]) @ v  (100 half-units) ----
    if (bid < 100) {
        int l = bid >> 1, half = bid & 1;
        const float* a  = s + A_OFF + half * 512;
        const float* Bl = s + B_OFF + l * H + half * 512;
        const float* vv = attn_v_W + half * 512;
        float p = 0.f;
#pragma unroll
        for (int jj = t; jj < 512; jj += 256)
            p = fmaf(fmaxf(a[jj] + Bl[jj], 0.f), vv[jj], p);
#pragma unroll
        for (int o = 16; o; o >>= 1) p += __shfl_xor_sync(0xffffffffu, p, o);
        if (lane == 0) ws[warp] = p;
        __syncthreads();
        if (t == 0) {
            float acc = ws[0];
#pragma unroll
            for (int w = 1; w < 8; ++w) acc += ws[w];
            atomicAdd(&s[SE_OFF + l], acc);
        }
    }
    grid_bar(2, NBLK);

    // ---- P3: softmax + attn_applied (blocks 0..7), attw/emb (block 8) ----
    if (bid <= 8) {
        float* se = sm;        // [50]
        float* sw = sm + 64;   // [50]
        __syncthreads();
        if (t < L) se[t] = s[SE_OFF + t];
        __syncthreads();
        if (t < L) {
            float m = -3.0e38f;
#pragma unroll
            for (int l = 0; l < L; ++l) m = fmaxf(m, se[l]);
            float sum = 0.f;
#pragma unroll
            for (int l = 0; l < L; ++l) sum += expf(se[l] - m);
            sw[t] = expf(se[t] - m) / sum;
        }
        __syncthreads();
        float* xin = s + XIN_OFF;
        if (bid < 8) {
            int col = bid * 256 + t;               // 0..2047
            float acc = 0.f;
#pragma unroll 10
            for (int l = 0; l < L; ++l)
                acc = fmaf(sw[l], enc[l * ENC + col], acc);
            xin[H + col] = acc;
        } else {
            if (t < L) attw_out[t] = sw[t];
            int id = idx[0];
            for (int i = t; i < H; i += 256)
                xin[i] = emb[(size_t)id * H + i];
        }
    }
    grid_bar(3, NBLK);

    // ---- P4: xpre += xin @ comb_W   (64 k-splits of 48) ----
    if (bid < 64) {
        int j = t * 4;
        int k0 = bid * 48;
        const float* Wp = comb_W + (size_t)k0 * H + j;
        float a0 = 0.f, a1 = 0.f, a2 = 0.f, a3 = 0.f;
#pragma unroll 8
        for (int k = 0; k < 48; ++k) {
            float xv = s[XIN_OFF + k0 + k];
            float4 w = *(const float4*)Wp;
            a0 = fmaf(xv, w.x, a0); a1 = fmaf(xv, w.y, a1);
            a2 = fmaf(xv, w.z, a2); a3 = fmaf(xv, w.w, a3);
            Wp += H;
        }
        atomicAdd(&s[XPRE_OFF + j],     a0); atomicAdd(&s[XPRE_OFF + j + 1], a1);
        atomicAdd(&s[XPRE_OFF + j + 2], a2); atomicAdd(&s[XPRE_OFF + j + 3], a3);
    }
    grid_bar(4, NBLK);

    // ---- P5: gi += relu(xpre) @ gru_wih  (3 j-tiles x 32 k-splits) ----
    if (bid < 96) {
        int ju = bid % 3, ku = bid / 3;
        int j = ju * 1024 + t * 4;
        int k0 = ku * 32;
        const float* Wp = gru_wih + (size_t)k0 * H3 + j;
        float a0 = 0.f, a1 = 0.f, a2 = 0.f, a3 = 0.f;
#pragma unroll 8
        for (int k = 0; k < 32; ++k) {
            float xv = fmaxf(s[XPRE_OFF + k0 + k], 0.f);
            float4 w = *(const float4*)Wp;
            a0 = fmaf(xv, w.x, a0); a1 = fmaf(xv, w.y, a1);
            a2 = fmaf(xv, w.z, a2); a3 = fmaf(xv, w.w, a3);
            Wp += H3;
        }
        atomicAdd(&s[GI_OFF + j],     a0); atomicAdd(&s[GI_OFF + j + 1], a1);
        atomicAdd(&s[GI_OFF + j + 2], a2); atomicAdd(&s[GI_OFF + j + 3], a3);
    }
    grid_bar(5, NBLK);

    // ---- P6: GRU gates -> h_new (blocks 0..3) ----
    if (bid < 4) {
        int i = bid * 256 + t;
        const float* gi = s + GI_OFF;
        const float* gh = s + GH_OFF;
        float r = 1.f / (1.f + expf(-(gi[i] + gh[i])));
        float z = 1.f / (1.f + expf(-(gi[H + i] + gh[H + i])));
        float n = tanhf(gi[2 * H + i] + r * gh[2 * H + i]);
        float hn = (1.f - z) * n + z * hidden[i];
        s[HNEW_OFF + i] = hn;
        hnew_out[i] = hn;
    }
}

// ---------------------------------------------------------------------------
// Vocab GEMV with EXPLICIT 16-deep load batching (MLP) + fused log-softmax.
// 394 blocks: 197 j-tiles x 2 k-splits of 512. 256 threads, 1 col/thread.
// __launch_bounds__(256,4): regs<=64 (16-float batch fits, no spill),
// 592 resident slots >= 394 -> grid-bar safe.
// logits pre-initialized with bias by the chain kernel.
// ---------------------------------------------------------------------------
#define JT 197
#define KCH 512
__global__ void __launch_bounds__(256, 4)
logits_kernel(const float* __restrict__ hnew,
              const float* __restrict__ W,
              float* __restrict__ logits,
              float* __restrict__ gsum) {
    __shared__ float hs[KCH];
    __shared__ float lse_s;
    const unsigned NBLK = gridDim.x;   // 394
    int t = threadIdx.x;
    int tile = blockIdx.x % JT;
    int ks   = blockIdx.x / JT;        // 0..1
    int k0 = ks * KCH;

    for (int i = t; i < KCH; i += 256) hs[i] = hnew[k0 + i];
    __syncthreads();

    int j = tile * 256 + t;
    if (j < V) {
        float acc = 0.f;
        const float* Wp = W + (size_t)k0 * V + j;
        for (int kk = 0; kk < KCH; kk += 16) {
            float w[16];
#pragma unroll
            for (int q = 0; q < 16; ++q)
                w[q] = Wp[(size_t)q * V];        // 16 independent LDGs
#pragma unroll
            for (int q = 0; q < 16; ++q)
                acc = fmaf(hs[kk + q], w[q], acc);
            Wp += (size_t)16 * V;
        }
        atomicAdd(&logits[j], acc);
    }
    grid_bar(6, NBLK);

    // exp-sum over final logits (gsum zeroed by chain P0)
    {
        int gid = blockIdx.x * 256 + t, stride = NBLK * 256;
        float ex = 0.f;
        for (int jj = gid; jj < V; jj += stride) ex += expf(logits[jj]);
#pragma unroll
        for (int o = 16; o; o >>= 1) ex += __shfl_xor_sync(0xffffffffu, ex, o);
        if ((t & 31) == 0 && ex != 0.f) atomicAdd(gsum, ex);
    }

    // barrier 7 with lse pickup between spin and depart
    __threadfence();
    __syncthreads();
    if (t == 0) {
        atomicAdd(&g_arrive[7], 1u);
        while (*(volatile unsigned*)&g_arrive[7] < NBLK) __nanosleep(64);
        lse_s = logf(*(volatile float*)gsum);
        unsigned d = atomicAdd(&g_depart[7], 1u);
        if (d == NBLK - 1u) {
            *(volatile unsigned*)&g_depart[7] = 0u;
            __threadfence();
            *(volatile unsigned*)&g_arrive[7] = 0u;
        }
    }
    __syncthreads();

    {
        int gid = blockIdx.x * 256 + t, stride = NBLK * 256;
        float lse = lse_s;
        for (int jj = gid; jj < V; jj += stride) logits[jj] -= lse;
    }
}

// ---------------------------------------------------------------------------
extern "C" void kernel_launch(void* const* d_in, const int* in_sizes, int n_in,
                              void* d_out, int out_size) {
    const int*   idx      = (const int*)d_in[0];
    const float* hidden   = (const float*)d_in[1];
    const float* enc      = (const float*)d_in[2];
    const float* emb      = (const float*)d_in[3];
    const float* attn_w_W = (const float*)d_in[4];
    const float* attn_w_b = (const float*)d_in[5];
    const float* attn_v_W = (const float*)d_in[6];
    const float* attn_v_b = (const float*)d_in[7];
    const float* comb_W   = (const float*)d_in[8];
    const float* comb_b   = (const float*)d_in[9];
    const float* gru_wih  = (const float*)d_in[10];
    const float* gru_bih  = (const float*)d_in[11];
    const float* gru_whh  = (const float*)d_in[12];
    const float* gru_bhh  = (const float*)d_in[13];
    const float* out_W    = (const float*)d_in[14];
    const float* out_b    = (const float*)d_in[15];
    float* out = (float*)d_out;   // [V logprobs][H h_new][L attn_weights]

    float* s = nullptr;
    cudaGetSymbolAddress((void**)&s, g_scratch);

    fused_chain_kernel<<<296, 256>>>(hidden, enc, emb, idx,
                                     attn_w_W, attn_w_b, attn_v_W, attn_v_b,
                                     comb_W, comb_b, gru_wih, gru_bih,
                                     gru_whh, gru_bhh, out_b,
                                     s, out, out + V, out + V + H);

    logits_kernel<<<JT * 2, 256>>>(s + HNEW_OFF, out_W, out, s + SUM_OFF);
}